// round 4
// baseline (speedup 1.0000x reference)
#include <cuda_runtime.h>

typedef unsigned long long ull;

#define B_ 2048
#define T_ 128
#define D_ 128
#define H_ 64
#define G_ 256   // 4*H

// 128 MB scratch for XZ1, layout [t][b][g]
__device__ float g_xz1[(size_t)T_ * B_ * G_];

// ---------------- f32x2 helpers ----------------
__device__ __forceinline__ ull pack2(float lo, float hi) {
    ull r; asm("mov.b64 %0,{%1,%2};" : "=l"(r) : "f"(lo), "f"(hi)); return r;
}
__device__ __forceinline__ ull ffma2(ull a, ull b, ull c) {
    ull d; asm("fma.rn.f32x2 %0,%1,%2,%3;" : "=l"(d) : "l"(a), "l"(b), "l"(c)); return d;
}
__device__ __forceinline__ float2 unpack2(ull v) {
    float2 f; asm("mov.b64 {%0,%1},%2;" : "=f"(f.x), "=f"(f.y) : "l"(v)); return f;
}
__device__ __forceinline__ float sigf(float x) {
    return __fdividef(1.f, 1.f + __expf(-x));
}
__device__ __forceinline__ float tanhf_(float x) {
    return 2.f * __fdividef(1.f, 1.f + __expf(-2.f * x)) - 1.f;
}

// ---------------------------------------------------------------------------
// Kernel 1: XZ1[t][b][g] = sum_d x[m][d] * W1[d][g] + b1[g]   (m = b*T + t)
// Persistent: grid=148 CTAs x 512 thr. W1 K-packed in smem (ull = (W[2k],W[2k+1])).
// Tiles of 16 rows; x tile stored as [kk][row] ull of (x[r][2kk], x[r][2kk+1])
// (contiguous in gmem). Double-buffered with register prefetch.
// ---------------------------------------------------------------------------
#define NT 16384          // (B*T)/16 tiles
#define XPAD 18           // ull per kk-row (16 + 2 pad, keeps 16B alignment)
#define NCTA1 148

__global__ void __launch_bounds__(512, 1) xz1_gemm_kernel(
    const float* __restrict__ x, const float* __restrict__ W1,
    const float* __restrict__ b1)
{
    extern __shared__ ull sh[];
    ull* W1p = sh;                 // [64][256] = 16384 ull
    ull* xt  = sh + 16384;         // 2 buffers x [64][XPAD]

    const int tid = threadIdx.x;
    const int g = tid & 255;       // gate column
    const int rh = tid >> 8;       // row half: rows rh*8 .. rh*8+7

    for (int i = tid; i < 16384; i += 512) {
        int kk = i >> 8, gg = i & 255;
        W1p[i] = pack2(W1[(2 * kk) * G_ + gg], W1[(2 * kk + 1) * G_ + gg]);
    }
    const float bias = b1[g];

    const int r_ld = tid >> 5, d4 = tid & 31;    // tile-load mapping
    const float4* xv4 = (const float4*)x;

    int tile = blockIdx.x;
    float4 pf = make_float4(0.f, 0.f, 0.f, 0.f);
    if (tile < NT) pf = xv4[(size_t)(tile * 16 + r_ld) * 32 + d4];
    __syncthreads();                 // W1p ready
    xt[(2 * d4) * XPAD + r_ld]     = pack2(pf.x, pf.y);
    xt[(2 * d4 + 1) * XPAD + r_ld] = pack2(pf.z, pf.w);
    __syncthreads();

    int buf = 0;
    while (tile < NT) {
        const int nxt = tile + NCTA1;
        const bool has = (nxt < NT);
        float4 nf;
        if (has) nf = xv4[(size_t)(nxt * 16 + r_ld) * 32 + d4];

        const ull* xb = xt + buf * (64 * XPAD) + rh * 8;
        ull acc[8];
        #pragma unroll
        for (int j = 0; j < 8; j++) acc[j] = 0ull;

        #pragma unroll 8
        for (int kk = 0; kk < 64; kk++) {
            ull w = W1p[kk * 256 + g];                      // LDS.64 coalesced
            const ull* xr = xb + kk * XPAD;
            ulonglong2 q0 = *(const ulonglong2*)(xr);       // LDS.128 bcast
            ulonglong2 q1 = *(const ulonglong2*)(xr + 2);
            ulonglong2 q2 = *(const ulonglong2*)(xr + 4);
            ulonglong2 q3 = *(const ulonglong2*)(xr + 6);
            acc[0] = ffma2(q0.x, w, acc[0]); acc[1] = ffma2(q0.y, w, acc[1]);
            acc[2] = ffma2(q1.x, w, acc[2]); acc[3] = ffma2(q1.y, w, acc[3]);
            acc[4] = ffma2(q2.x, w, acc[4]); acc[5] = ffma2(q2.y, w, acc[5]);
            acc[6] = ffma2(q3.x, w, acc[6]); acc[7] = ffma2(q3.y, w, acc[7]);
        }

        #pragma unroll
        for (int j = 0; j < 8; j++) {
            float2 v = unpack2(acc[j]);
            int m = tile * 16 + rh * 8 + j;                 // b = m>>7, t = m&127
            g_xz1[(size_t)(m & 127) * (B_ * G_) + (size_t)(m >> 7) * G_ + g]
                = bias + v.x + v.y;
        }

        __syncthreads();             // everyone done reading buf set
        if (has) {
            ull* nb = xt + (buf ^ 1) * (64 * XPAD);
            nb[(2 * d4) * XPAD + r_ld]     = pack2(nf.x, nf.y);
            nb[(2 * d4 + 1) * XPAD + r_ld] = pack2(nf.z, nf.w);
        }
        __syncthreads();
        buf ^= 1;
        tile = nxt;
    }
}
#define XZ1_SMEM ((16384 + 2 * 64 * XPAD) * (int)sizeof(ull))

// ---------------------------------------------------------------------------
// Kernel 2: fused persistent 2-layer LSTM scan. K-paired f32x2, no splats.
// 128 CTAs x 256 threads; CTA owns BT=16 batch rows. Thread = 1 gate col x 16 rows.
// h stored as [kk][b] ull = (h[2kk][b], h[2kk+1][b]); halves written scalar.
// ---------------------------------------------------------------------------
#define BT 16
#define ZP 258
// smem (ull): U1p 8192 | W2p 8192 | U2p 8192 | h1p 512 | h2p 512  = 25600 ull
// smem (flt): b2s 256  | zs 16*258 = 4128                          = 4384 f
#define SCAN_SMEM (25600 * (int)sizeof(ull) + (256 + BT * ZP) * (int)sizeof(float))

__global__ void __launch_bounds__(256, 1) lstm_scan_kernel(
    const float* __restrict__ U1g, const float* __restrict__ W2g,
    const float* __restrict__ U2g, const float* __restrict__ b2g,
    float* __restrict__ out)
{
    extern __shared__ ull smu[];
    ull* U1p = smu;              // [32][256]
    ull* W2p = smu + 8192;
    ull* U2p = smu + 16384;
    ull* h1p = smu + 24576;      // [32][16]
    ull* h2p = smu + 25088;
    float* b2s = (float*)(smu + 25600);
    float* zs  = b2s + 256;      // [16][ZP]
    float* h1f = (float*)h1p;
    float* h2f = (float*)h2p;

    const int tid = threadIdx.x;
    const int g = tid;                    // GEMM column
    const int b0g = blockIdx.x * BT;

    for (int i = tid; i < 8192; i += 256) {
        int kk = i >> 8, gg = i & 255;
        U1p[i] = pack2(U1g[(2 * kk) * G_ + gg], U1g[(2 * kk + 1) * G_ + gg]);
        W2p[i] = pack2(W2g[(2 * kk) * G_ + gg], W2g[(2 * kk + 1) * G_ + gg]);
        U2p[i] = pack2(U2g[(2 * kk) * G_ + gg], U2g[(2 * kk + 1) * G_ + gg]);
    }
    b2s[tid] = b2g[tid];
    for (int i = tid; i < 1024; i += 256) h1p[i] = 0ull;   // zeroes h1p + h2p
    const float b2v = b2g[tid];

    // elementwise mapping
    const int eh = tid >> 2;
    const int eb0 = (tid & 3) << 2;
    const int ehk = (eh >> 1) * 32 + (eh & 1);   // float index base into h*f: (kk*16+b)*2+half
    float c1[4] = {0.f, 0.f, 0.f, 0.f};
    float c2[4] = {0.f, 0.f, 0.f, 0.f};
    __syncthreads();

    const float* xzb = g_xz1 + (size_t)b0g * G_ + g;

    for (int t = 0; t < T_; t++) {
        // ---- phase A: z1 = XZ1[t] + h1_prev @ U1 ----
        float xzv[BT];
        {
            const float* xzp = xzb + (size_t)t * (B_ * G_);
            #pragma unroll
            for (int j = 0; j < BT; j++) xzv[j] = xzp[(size_t)j * G_];
        }
        ull acc[BT];
        #pragma unroll
        for (int j = 0; j < BT; j++) acc[j] = 0ull;

        #pragma unroll 4
        for (int kk = 0; kk < 32; kk++) {
            ull u = U1p[kk * 256 + g];
            const ull* hb = h1p + kk * 16;
            ulonglong2 a0 = *(const ulonglong2*)(hb);
            ulonglong2 a1 = *(const ulonglong2*)(hb + 2);
            ulonglong2 a2 = *(const ulonglong2*)(hb + 4);
            ulonglong2 a3 = *(const ulonglong2*)(hb + 6);
            ulonglong2 a4 = *(const ulonglong2*)(hb + 8);
            ulonglong2 a5 = *(const ulonglong2*)(hb + 10);
            ulonglong2 a6 = *(const ulonglong2*)(hb + 12);
            ulonglong2 a7 = *(const ulonglong2*)(hb + 14);
            acc[0]  = ffma2(a0.x, u, acc[0]);  acc[1]  = ffma2(a0.y, u, acc[1]);
            acc[2]  = ffma2(a1.x, u, acc[2]);  acc[3]  = ffma2(a1.y, u, acc[3]);
            acc[4]  = ffma2(a2.x, u, acc[4]);  acc[5]  = ffma2(a2.y, u, acc[5]);
            acc[6]  = ffma2(a3.x, u, acc[6]);  acc[7]  = ffma2(a3.y, u, acc[7]);
            acc[8]  = ffma2(a4.x, u, acc[8]);  acc[9]  = ffma2(a4.y, u, acc[9]);
            acc[10] = ffma2(a5.x, u, acc[10]); acc[11] = ffma2(a5.y, u, acc[11]);
            acc[12] = ffma2(a6.x, u, acc[12]); acc[13] = ffma2(a6.y, u, acc[13]);
            acc[14] = ffma2(a7.x, u, acc[14]); acc[15] = ffma2(a7.y, u, acc[15]);
        }
        #pragma unroll
        for (int j = 0; j < BT; j++) {
            float2 v = unpack2(acc[j]);
            zs[j * ZP + g] = xzv[j] + v.x + v.y;
        }
        __syncthreads();

        // ---- phase B: layer-1 gates (act = tanh) ----
        {
            #pragma unroll
            for (int j = 0; j < 4; j++) {
                const float* zr = zs + (eb0 + j) * ZP + eh;
                float ig = sigf(zr[0]);
                float fg = sigf(zr[64]);
                float gg = tanhf_(zr[128]);
                float og = sigf(zr[192]);
                c1[j] = fmaf(fg, c1[j], ig * gg);
                h1f[ehk + (eb0 + j) * 2] = og * tanhf_(c1[j]);
            }
        }
        __syncthreads();

        // ---- phase C: z2 = h1_new @ W2 + h2_prev @ U2 + b2 ----
        ull acc2[BT];
        #pragma unroll
        for (int j = 0; j < BT; j++) acc2[j] = 0ull;

        #pragma unroll 2
        for (int kk = 0; kk < 32; kk++) {
            ull w = W2p[kk * 256 + g];
            ull u = U2p[kk * 256 + g];
            const ull* hb = h1p + kk * 16;
            const ull* pb = h2p + kk * 16;
            #pragma unroll
            for (int q = 0; q < 8; q++) {
                ulonglong2 a = *(const ulonglong2*)(hb + 2 * q);
                ulonglong2 p = *(const ulonglong2*)(pb + 2 * q);
                acc2[2 * q]     = ffma2(a.x, w, ffma2(p.x, u, acc2[2 * q]));
                acc2[2 * q + 1] = ffma2(a.y, w, ffma2(p.y, u, acc2[2 * q + 1]));
            }
        }
        #pragma unroll
        for (int j = 0; j < BT; j++) {
            float2 v = unpack2(acc2[j]);
            zs[j * ZP + g] = b2v + v.x + v.y;
        }
        __syncthreads();

        // ---- phase D: layer-2 gates (act = sigmoid) + output store ----
        {
            #pragma unroll
            for (int j = 0; j < 4; j++) {
                const float* zr = zs + (eb0 + j) * ZP + eh;
                float ig = sigf(zr[0]);
                float fg = sigf(zr[64]);
                float gg = sigf(zr[128]);
                float og = sigf(zr[192]);
                c2[j] = fmaf(fg, c2[j], ig * gg);
                float hn = og * sigf(c2[j]);
                h2f[ehk + (eb0 + j) * 2] = hn;
                out[(size_t)(b0g + eb0 + j) * (T_ * H_) + t * H_ + eh] = hn;
            }
        }
        __syncthreads();
    }
}

// ---------------------------------------------------------------------------
extern "C" void kernel_launch(void* const* d_in, const int* in_sizes, int n_in,
                              void* d_out, int out_size)
{
    const float* x  = (const float*)d_in[0];
    const float* W1 = (const float*)d_in[1];
    const float* U1 = (const float*)d_in[2];
    const float* b1 = (const float*)d_in[3];
    const float* W2 = (const float*)d_in[4];
    const float* U2 = (const float*)d_in[5];
    const float* b2 = (const float*)d_in[6];
    float* out = (float*)d_out;

    cudaFuncSetAttribute(xz1_gemm_kernel,
                         cudaFuncAttributeMaxDynamicSharedMemorySize, XZ1_SMEM);
    xz1_gemm_kernel<<<NCTA1, 512, XZ1_SMEM>>>(x, W1, b1);

    cudaFuncSetAttribute(lstm_scan_kernel,
                         cudaFuncAttributeMaxDynamicSharedMemorySize, SCAN_SMEM);
    lstm_scan_kernel<<<B_ / BT, 256, SCAN_SMEM>>>(U1, W2, U2, b2, out);
}

// round 5
// speedup vs baseline: 1.7037x; 1.7037x over previous
#include <cuda_runtime.h>

typedef unsigned long long ull;

#define B_ 2048
#define T_ 128
#define D_ 128
#define H_ 64
#define G_ 256   // 4*H

// 128 MB scratch for XZ1, layout [t][b][g]
__device__ float g_xz1[(size_t)T_ * B_ * G_];

// ---------------- f32x2 helpers ----------------
__device__ __forceinline__ ull splat2(float v) {
    ull r; asm("mov.b64 %0,{%1,%1};" : "=l"(r) : "f"(v)); return r;
}
__device__ __forceinline__ ull pack2(float lo, float hi) {
    ull r; asm("mov.b64 %0,{%1,%2};" : "=l"(r) : "f"(lo), "f"(hi)); return r;
}
__device__ __forceinline__ ull ffma2(ull a, ull b, ull c) {
    ull d; asm("fma.rn.f32x2 %0,%1,%2,%3;" : "=l"(d) : "l"(a), "l"(b), "l"(c)); return d;
}
__device__ __forceinline__ float2 unpack2(ull v) {
    float2 f; asm("mov.b64 {%0,%1},%2;" : "=f"(f.x), "=f"(f.y) : "l"(v)); return f;
}
__device__ __forceinline__ float sigf(float x) {
    return __fdividef(1.f, 1.f + __expf(-x));
}
__device__ __forceinline__ float tanhf_(float x) {
    return 2.f * __fdividef(1.f, 1.f + __expf(-2.f * x)) - 1.f;
}

// ---------------------------------------------------------------------------
// Kernel 1: XZ1[t][b][g] = sum_d x[m][d] * W1[d][g] + b1[g]  (round-3 version)
// Block = 32 rows x 256 cols. Rows packed as f32x2 pairs (r, r+16) in smem.
// ---------------------------------------------------------------------------
#define GR 32
__global__ void __launch_bounds__(256) xz1_gemm_kernel(
    const float* __restrict__ x, const float* __restrict__ W1,
    const float* __restrict__ b1)
{
    __shared__ ull xp[D_ * 16];   // [d][pair], pair p = rows (p, p+16)
    const int tid = threadIdx.x;
    const int m0 = blockIdx.x * GR;

    const float4* xv = (const float4*)x;
    #pragma unroll
    for (int i = 0; i < 2; i++) {
        int u = tid + i * 256;
        int p = u >> 5, c4 = u & 31;
        float4 a = xv[(size_t)(m0 + p) * 32 + c4];
        float4 b = xv[(size_t)(m0 + p + 16) * 32 + c4];
        xp[(4 * c4 + 0) * 16 + p] = pack2(a.x, b.x);
        xp[(4 * c4 + 1) * 16 + p] = pack2(a.y, b.y);
        xp[(4 * c4 + 2) * 16 + p] = pack2(a.z, b.z);
        xp[(4 * c4 + 3) * 16 + p] = pack2(a.w, b.w);
    }
    __syncthreads();

    const int g = tid;
    ull bias = splat2(b1[g]);
    ull acc[16];
    #pragma unroll
    for (int p = 0; p < 16; p++) acc[p] = bias;

    const float* Wp = W1 + g;
    #pragma unroll 2
    for (int k = 0; k < D_; k += 4) {
        float w0 = Wp[(k + 0) * G_];
        float w1 = Wp[(k + 1) * G_];
        float w2 = Wp[(k + 2) * G_];
        float w3 = Wp[(k + 3) * G_];
        ull ws0 = splat2(w0), ws1 = splat2(w1), ws2 = splat2(w2), ws3 = splat2(w3);
        #pragma unroll
        for (int kk = 0; kk < 4; kk++) {
            ull ws = (kk == 0) ? ws0 : (kk == 1) ? ws1 : (kk == 2) ? ws2 : ws3;
            const ull* xr = xp + (k + kk) * 16;
            #pragma unroll
            for (int p = 0; p < 16; p += 2) {
                ulonglong2 q = *(const ulonglong2*)(xr + p);
                acc[p]     = ffma2(q.x, ws, acc[p]);
                acc[p + 1] = ffma2(q.y, ws, acc[p + 1]);
            }
        }
    }

    #pragma unroll
    for (int p = 0; p < 16; p++) {
        float2 v = unpack2(acc[p]);
        int m = m0 + p;
        g_xz1[(size_t)(m & 127) * (B_ * G_) + (size_t)(m >> 7) * G_ + g] = v.x;
        m = m0 + p + 16;
        g_xz1[(size_t)(m & 127) * (B_ * G_) + (size_t)(m >> 7) * G_ + g] = v.y;
    }
}

// ---------------------------------------------------------------------------
// Kernel 2: fused persistent 2-layer LSTM scan. K-paired f32x2, splat-free.
// 128 CTAs x 512 threads (16 warps/SM); CTA owns BT=16 batch rows.
// GEMM mapping: thread = 1 gate col x 8 rows (rh = tid>>8 selects row half).
// h stored K-paired: h*p[kk][b] = (h[2kk][b], h[2kk+1][b]).
// ---------------------------------------------------------------------------
#define BT 16
#define ZP 258
// smem (ull): U1p 8192 | W2p 8192 | U2p 8192 | h1p 512 | h2p 512  = 25600 ull
// smem (flt): zs 16*258 = 4128
#define SCAN_SMEM (25600 * (int)sizeof(ull) + (BT * ZP) * (int)sizeof(float))

__global__ void __launch_bounds__(512, 1) lstm_scan_kernel(
    const float* __restrict__ U1g, const float* __restrict__ W2g,
    const float* __restrict__ U2g, const float* __restrict__ b2g,
    float* __restrict__ out)
{
    extern __shared__ ull smu[];
    ull* U1p = smu;              // [32][256]
    ull* W2p = smu + 8192;
    ull* U2p = smu + 16384;
    ull* h1p = smu + 24576;      // [32][16] K-paired
    ull* h2p = smu + 25088;
    float* zs = (float*)(smu + 25600);   // [16][ZP]
    float* h1f = (float*)h1p;
    float* h2f = (float*)h2p;

    const int tid = threadIdx.x;
    const int g = tid & 255;             // GEMM column
    const int rowbase = (tid >> 8) << 3; // 0 or 8
    const int b0g = blockIdx.x * BT;

    for (int i = tid; i < 8192; i += 512) {
        int kk = i >> 8, gg = i & 255;
        U1p[i] = pack2(U1g[(2 * kk) * G_ + gg], U1g[(2 * kk + 1) * G_ + gg]);
        W2p[i] = pack2(W2g[(2 * kk) * G_ + gg], W2g[(2 * kk + 1) * G_ + gg]);
        U2p[i] = pack2(U2g[(2 * kk) * G_ + gg], U2g[(2 * kk + 1) * G_ + gg]);
    }
    for (int i = tid; i < 1024; i += 512) h1p[i] = 0ull;   // zeroes h1p + h2p
    const float b2v = b2g[g];

    // elementwise mapping: thread -> (h = tid>>3, rows er0, er0+1)
    const int eh = tid >> 3;
    const int er0 = (tid & 7) << 1;
    const int ehbase = ((eh >> 1) << 5) + (eh & 1);  // float idx: +b*2
    float c1[2] = {0.f, 0.f};
    float c2[2] = {0.f, 0.f};
    __syncthreads();

    const float* xzb = g_xz1 + (size_t)(b0g + rowbase) * G_ + g;

    for (int t = 0; t < T_; t++) {
        // ---- phase A: z1 = XZ1[t] + h1_prev @ U1 ----
        float xzv[8];
        {
            const float* xzp = xzb + (size_t)t * (B_ * G_);
            #pragma unroll
            for (int j = 0; j < 8; j++) xzv[j] = xzp[(size_t)j * G_];
        }
        ull acc[8];
        #pragma unroll
        for (int j = 0; j < 8; j++) acc[j] = 0ull;

        #pragma unroll 4
        for (int kk = 0; kk < 32; kk++) {
            ull u = U1p[kk * 256 + g];
            const ull* hb = h1p + kk * 16 + rowbase;
            ulonglong2 a0 = *(const ulonglong2*)(hb);
            ulonglong2 a1 = *(const ulonglong2*)(hb + 2);
            ulonglong2 a2 = *(const ulonglong2*)(hb + 4);
            ulonglong2 a3 = *(const ulonglong2*)(hb + 6);
            acc[0] = ffma2(a0.x, u, acc[0]); acc[1] = ffma2(a0.y, u, acc[1]);
            acc[2] = ffma2(a1.x, u, acc[2]); acc[3] = ffma2(a1.y, u, acc[3]);
            acc[4] = ffma2(a2.x, u, acc[4]); acc[5] = ffma2(a2.y, u, acc[5]);
            acc[6] = ffma2(a3.x, u, acc[6]); acc[7] = ffma2(a3.y, u, acc[7]);
        }
        #pragma unroll
        for (int j = 0; j < 8; j++) {
            float2 v = unpack2(acc[j]);
            zs[(rowbase + j) * ZP + g] = xzv[j] + v.x + v.y;
        }
        __syncthreads();

        // ---- phase B: layer-1 gates (act = tanh) ----
        #pragma unroll
        for (int j = 0; j < 2; j++) {
            int b = er0 + j;
            const float* zr = zs + b * ZP + eh;
            float ig = sigf(zr[0]);
            float fg = sigf(zr[64]);
            float gg = tanhf_(zr[128]);
            float og = sigf(zr[192]);
            c1[j] = fmaf(fg, c1[j], ig * gg);
            h1f[ehbase + b * 2] = og * tanhf_(c1[j]);
        }
        __syncthreads();

        // ---- phase C: z2 = h1_new @ W2 + h2_prev @ U2 + b2 ----
        ull acc2[8];
        #pragma unroll
        for (int j = 0; j < 8; j++) acc2[j] = 0ull;

        #pragma unroll 2
        for (int kk = 0; kk < 32; kk++) {
            ull w = W2p[kk * 256 + g];
            ull u = U2p[kk * 256 + g];
            const ull* hb = h1p + kk * 16 + rowbase;
            const ull* pb = h2p + kk * 16 + rowbase;
            ulonglong2 a0 = *(const ulonglong2*)(hb);
            ulonglong2 a1 = *(const ulonglong2*)(hb + 2);
            ulonglong2 a2 = *(const ulonglong2*)(hb + 4);
            ulonglong2 a3 = *(const ulonglong2*)(hb + 6);
            ulonglong2 p0 = *(const ulonglong2*)(pb);
            ulonglong2 p1 = *(const ulonglong2*)(pb + 2);
            ulonglong2 p2 = *(const ulonglong2*)(pb + 4);
            ulonglong2 p3 = *(const ulonglong2*)(pb + 6);
            acc2[0] = ffma2(a0.x, w, ffma2(p0.x, u, acc2[0]));
            acc2[1] = ffma2(a0.y, w, ffma2(p0.y, u, acc2[1]));
            acc2[2] = ffma2(a1.x, w, ffma2(p1.x, u, acc2[2]));
            acc2[3] = ffma2(a1.y, w, ffma2(p1.y, u, acc2[3]));
            acc2[4] = ffma2(a2.x, w, ffma2(p2.x, u, acc2[4]));
            acc2[5] = ffma2(a2.y, w, ffma2(p2.y, u, acc2[5]));
            acc2[6] = ffma2(a3.x, w, ffma2(p3.x, u, acc2[6]));
            acc2[7] = ffma2(a3.y, w, ffma2(p3.y, u, acc2[7]));
        }
        #pragma unroll
        for (int j = 0; j < 8; j++) {
            float2 v = unpack2(acc2[j]);
            zs[(rowbase + j) * ZP + g] = b2v + v.x + v.y;
        }
        __syncthreads();

        // ---- phase D: layer-2 gates (act = sigmoid) + output store ----
        #pragma unroll
        for (int j = 0; j < 2; j++) {
            int b = er0 + j;
            const float* zr = zs + b * ZP + eh;
            float ig = sigf(zr[0]);
            float fg = sigf(zr[64]);
            float gg = sigf(zr[128]);
            float og = sigf(zr[192]);
            c2[j] = fmaf(fg, c2[j], ig * gg);
            float hn = og * sigf(c2[j]);
            h2f[ehbase + b * 2] = hn;
            out[(size_t)(b0g + b) * (T_ * H_) + t * H_ + eh] = hn;
        }
        __syncthreads();
    }
}

// ---------------------------------------------------------------------------
extern "C" void kernel_launch(void* const* d_in, const int* in_sizes, int n_in,
                              void* d_out, int out_size)
{
    const float* x  = (const float*)d_in[0];
    const float* W1 = (const float*)d_in[1];
    const float* U1 = (const float*)d_in[2];
    const float* b1 = (const float*)d_in[3];
    const float* W2 = (const float*)d_in[4];
    const float* U2 = (const float*)d_in[5];
    const float* b2 = (const float*)d_in[6];
    float* out = (float*)d_out;

    xz1_gemm_kernel<<<(B_ * T_) / GR, 256>>>(x, W1, b1);

    cudaFuncSetAttribute(lstm_scan_kernel,
                         cudaFuncAttributeMaxDynamicSharedMemorySize, SCAN_SMEM);
    lstm_scan_kernel<<<B_ / BT, 512, SCAN_SMEM>>>(U1, W2, U2, b2, out);
}

// round 9
// speedup vs baseline: 2.2339x; 1.3112x over previous
#include <cuda_runtime.h>

typedef unsigned long long ull;

#define B_ 2048
#define T_ 128
#define D_ 128
#define H_ 64
#define G_ 256   // 4*H

// 128 MB scratch for XZ1, layout [t][b][g]
__device__ float g_xz1[(size_t)T_ * B_ * G_];

// ---------------- f32x2 helpers ----------------
__device__ __forceinline__ ull splat2(float v) {
    ull r; asm("mov.b64 %0,{%1,%1};" : "=l"(r) : "f"(v)); return r;
}
__device__ __forceinline__ ull pack2(float lo, float hi) {
    ull r; asm("mov.b64 %0,{%1,%2};" : "=l"(r) : "f"(lo), "f"(hi)); return r;
}
__device__ __forceinline__ ull ffma2(ull a, ull b, ull c) {
    ull d; asm("fma.rn.f32x2 %0,%1,%2,%3;" : "=l"(d) : "l"(a), "l"(b), "l"(c)); return d;
}
__device__ __forceinline__ float2 unpack2(ull v) {
    float2 f; asm("mov.b64 {%0,%1},%2;" : "=f"(f.x), "=f"(f.y) : "l"(v)); return f;
}
__device__ __forceinline__ float sigf(float x) {
    return __fdividef(1.f, 1.f + __expf(-x));
}
__device__ __forceinline__ float tanhf_(float x) {
    return 2.f * __fdividef(1.f, 1.f + __expf(-2.f * x)) - 1.f;
}

// ---------------------------------------------------------------------------
// Kernel 1: XZ1[t][b][g] = sum_d x[m][d] * W1[d][g] + b1[g]  (m = b*T + t)
// Block = 32 rows x 256 thr. Thread = 2 gate cols x 8 row-pairs.
// x rows packed f32x2 (r, r+16) in smem (same staging as round-3 kernel).
// ---------------------------------------------------------------------------
#define GR 32
__global__ void __launch_bounds__(256) xz1_gemm_kernel(
    const float* __restrict__ x, const float* __restrict__ W1,
    const float* __restrict__ b1)
{
    __shared__ ull xp[D_ * 16];   // [d][pair], pair p = rows (p, p+16)
    const int tid = threadIdx.x;
    const int m0 = blockIdx.x * GR;

    const float4* xv = (const float4*)x;
    #pragma unroll
    for (int i = 0; i < 2; i++) {
        int u = tid + i * 256;
        int p = u >> 5, c4 = u & 31;
        float4 a = xv[(size_t)(m0 + p) * 32 + c4];
        float4 b = xv[(size_t)(m0 + p + 16) * 32 + c4];
        xp[(4 * c4 + 0) * 16 + p] = pack2(a.x, b.x);
        xp[(4 * c4 + 1) * 16 + p] = pack2(a.y, b.y);
        xp[(4 * c4 + 2) * 16 + p] = pack2(a.z, b.z);
        xp[(4 * c4 + 3) * 16 + p] = pack2(a.w, b.w);
    }
    __syncthreads();

    const int cp = tid & 127;            // cols 2cp, 2cp+1
    const int rh = (tid >> 7) << 3;      // row-pairs rh..rh+7

    const float2 bias = *(const float2*)(b1 + 2 * cp);
    ull acc0[8], acc1[8];
    #pragma unroll
    for (int j = 0; j < 8; j++) { acc0[j] = splat2(bias.x); acc1[j] = splat2(bias.y); }

    const float2* Wp = (const float2*)W1 + cp;     // W1[k][2cp..2cp+1]
    #pragma unroll 4
    for (int k = 0; k < D_; k++) {
        float2 w = Wp[k * 128];
        ull ws0 = splat2(w.x), ws1 = splat2(w.y);
        const ull* xr = xp + k * 16 + rh;
        ulonglong2 q0 = *(const ulonglong2*)(xr);
        ulonglong2 q1 = *(const ulonglong2*)(xr + 2);
        ulonglong2 q2 = *(const ulonglong2*)(xr + 4);
        ulonglong2 q3 = *(const ulonglong2*)(xr + 6);
        acc0[0] = ffma2(q0.x, ws0, acc0[0]); acc1[0] = ffma2(q0.x, ws1, acc1[0]);
        acc0[1] = ffma2(q0.y, ws0, acc0[1]); acc1[1] = ffma2(q0.y, ws1, acc1[1]);
        acc0[2] = ffma2(q1.x, ws0, acc0[2]); acc1[2] = ffma2(q1.x, ws1, acc1[2]);
        acc0[3] = ffma2(q1.y, ws0, acc0[3]); acc1[3] = ffma2(q1.y, ws1, acc1[3]);
        acc0[4] = ffma2(q2.x, ws0, acc0[4]); acc1[4] = ffma2(q2.x, ws1, acc1[4]);
        acc0[5] = ffma2(q2.y, ws0, acc0[5]); acc1[5] = ffma2(q2.y, ws1, acc1[5]);
        acc0[6] = ffma2(q3.x, ws0, acc0[6]); acc1[6] = ffma2(q3.x, ws1, acc1[6]);
        acc0[7] = ffma2(q3.y, ws0, acc0[7]); acc1[7] = ffma2(q3.y, ws1, acc1[7]);
    }

    #pragma unroll
    for (int j = 0; j < 8; j++) {
        float2 va = unpack2(acc0[j]);   // col 2cp   : rows (p, p+16)
        float2 vb = unpack2(acc1[j]);   // col 2cp+1
        int m = m0 + rh + j;
        *(float2*)(g_xz1 + (size_t)(m & 127) * (B_ * G_)
                         + (size_t)(m >> 7) * G_ + 2 * cp) = make_float2(va.x, vb.x);
        m += 16;
        *(float2*)(g_xz1 + (size_t)(m & 127) * (B_ * G_)
                         + (size_t)(m >> 7) * G_ + 2 * cp) = make_float2(va.y, vb.y);
    }
}

// ---------------------------------------------------------------------------
// Kernel 2: fused persistent 2-layer LSTM scan. K-paired f32x2.
// 128 CTAs x 256 threads; CTA owns BT=16 batch rows.
// GEMM mapping: thread = 2 gate cols (ulonglong2 weight load) x 8 rows.
// Weights in smem as [kk][cp] ulonglong2 {col 2cp K-pair, col 2cp+1 K-pair}.
// h stored K-paired: h*p[kk][b] = (h[2kk][b], h[2kk+1][b]).
// ---------------------------------------------------------------------------
#define BT 16
#define ZP 258
// bytes: U1q 64K | W2q 64K | U2q 64K | h1p 4K | h2p 4K | zs 16*258*4
#define SCAN_SMEM (3 * 65536 + 2 * 4096 + BT * ZP * (int)sizeof(float))

__global__ void __launch_bounds__(256, 1) lstm_scan_kernel(
    const float* __restrict__ U1g, const float* __restrict__ W2g,
    const float* __restrict__ U2g, const float* __restrict__ b2g,
    float* __restrict__ out)
{
    extern __shared__ char smb[];
    ulonglong2* U1q = (ulonglong2*)smb;                    // [32][128]
    ulonglong2* W2q = (ulonglong2*)(smb + 65536);
    ulonglong2* U2q = (ulonglong2*)(smb + 131072);
    ull* h1p = (ull*)(smb + 196608);                       // [32][16]
    ull* h2p = (ull*)(smb + 196608 + 4096);
    float* zs = (float*)(smb + 196608 + 8192);             // [16][ZP]
    float* h1f = (float*)h1p;
    float* h2f = (float*)h2p;

    const int tid = threadIdx.x;
    const int cp = tid & 127;            // cols 2cp, 2cp+1
    const int rh = (tid >> 7) << 3;      // rows rh..rh+7
    const int b0g = blockIdx.x * BT;

    for (int i = tid; i < 4096; i += 256) {
        int kk = i >> 7, c = (i & 127) << 1;
        U1q[i] = make_ulonglong2(
            pack2(U1g[(2 * kk) * G_ + c],     U1g[(2 * kk + 1) * G_ + c]),
            pack2(U1g[(2 * kk) * G_ + c + 1], U1g[(2 * kk + 1) * G_ + c + 1]));
        W2q[i] = make_ulonglong2(
            pack2(W2g[(2 * kk) * G_ + c],     W2g[(2 * kk + 1) * G_ + c]),
            pack2(W2g[(2 * kk) * G_ + c + 1], W2g[(2 * kk + 1) * G_ + c + 1]));
        U2q[i] = make_ulonglong2(
            pack2(U2g[(2 * kk) * G_ + c],     U2g[(2 * kk + 1) * G_ + c]),
            pack2(U2g[(2 * kk) * G_ + c + 1], U2g[(2 * kk + 1) * G_ + c + 1]));
    }
    for (int i = tid; i < 1024; i += 256) h1p[i] = 0ull;   // zeroes h1p + h2p
    const float2 b2v = *(const float2*)(b2g + 2 * cp);

    // elementwise mapping: thread -> (h = tid>>2, 4 rows eb0..eb0+3)
    const int eh = tid >> 2;
    const int eb0 = (tid & 3) << 2;
    const int ehbase = ((eh >> 1) << 5) + (eh & 1);        // + b*2
    float c1[4] = {0.f, 0.f, 0.f, 0.f};
    float c2[4] = {0.f, 0.f, 0.f, 0.f};
    __syncthreads();

    const float* xzb = g_xz1 + (size_t)(b0g + rh) * G_ + 2 * cp;

    for (int t = 0; t < T_; t++) {
        // ---- phase A: z1 = XZ1[t] + h1_prev @ U1 ----
        float2 xzv[8];
        {
            const float* xzp = xzb + (size_t)t * (B_ * G_);
            #pragma unroll
            for (int j = 0; j < 8; j++)
                xzv[j] = *(const float2*)(xzp + (size_t)j * G_);
        }
        ull acc0[8], acc1[8];
        #pragma unroll
        for (int j = 0; j < 8; j++) { acc0[j] = 0ull; acc1[j] = 0ull; }

        #pragma unroll 4
        for (int kk = 0; kk < 32; kk++) {
            ulonglong2 uq = U1q[kk * 128 + cp];
            const ull* hb = h1p + kk * 16 + rh;
            ulonglong2 a0 = *(const ulonglong2*)(hb);
            ulonglong2 a1 = *(const ulonglong2*)(hb + 2);
            ulonglong2 a2 = *(const ulonglong2*)(hb + 4);
            ulonglong2 a3 = *(const ulonglong2*)(hb + 6);
            acc0[0] = ffma2(a0.x, uq.x, acc0[0]); acc1[0] = ffma2(a0.x, uq.y, acc1[0]);
            acc0[1] = ffma2(a0.y, uq.x, acc0[1]); acc1[1] = ffma2(a0.y, uq.y, acc1[1]);
            acc0[2] = ffma2(a1.x, uq.x, acc0[2]); acc1[2] = ffma2(a1.x, uq.y, acc1[2]);
            acc0[3] = ffma2(a1.y, uq.x, acc0[3]); acc1[3] = ffma2(a1.y, uq.y, acc1[3]);
            acc0[4] = ffma2(a2.x, uq.x, acc0[4]); acc1[4] = ffma2(a2.x, uq.y, acc1[4]);
            acc0[5] = ffma2(a2.y, uq.x, acc0[5]); acc1[5] = ffma2(a2.y, uq.y, acc1[5]);
            acc0[6] = ffma2(a3.x, uq.x, acc0[6]); acc1[6] = ffma2(a3.x, uq.y, acc1[6]);
            acc0[7] = ffma2(a3.y, uq.x, acc0[7]); acc1[7] = ffma2(a3.y, uq.y, acc1[7]);
        }
        #pragma unroll
        for (int j = 0; j < 8; j++) {
            float2 v0 = unpack2(acc0[j]);
            float2 v1 = unpack2(acc1[j]);
            *(float2*)(zs + (rh + j) * ZP + 2 * cp)
                = make_float2(xzv[j].x + v0.x + v0.y, xzv[j].y + v1.x + v1.y);
        }
        __syncthreads();

        // ---- phase B: layer-1 gates (act = tanh) ----
        #pragma unroll
        for (int j = 0; j < 4; j++) {
            int b = eb0 + j;
            const float* zr = zs + b * ZP + eh;
            float ig = sigf(zr[0]);
            float fg = sigf(zr[64]);
            float gg = tanhf_(zr[128]);
            float og = sigf(zr[192]);
            c1[j] = fmaf(fg, c1[j], ig * gg);
            h1f[ehbase + b * 2] = og * tanhf_(c1[j]);
        }
        __syncthreads();

        // ---- phase C: z2 = h1_new @ W2 + h2_prev @ U2 + b2 ----
        ull bcc0[8], bcc1[8];
        #pragma unroll
        for (int j = 0; j < 8; j++) { bcc0[j] = 0ull; bcc1[j] = 0ull; }

        #pragma unroll 2
        for (int kk = 0; kk < 32; kk++) {
            ulonglong2 wq = W2q[kk * 128 + cp];
            ulonglong2 uq = U2q[kk * 128 + cp];
            const ull* hb = h1p + kk * 16 + rh;
            const ull* pb = h2p + kk * 16 + rh;
            #pragma unroll
            for (int q = 0; q < 4; q++) {
                ulonglong2 a = *(const ulonglong2*)(hb + 2 * q);
                ulonglong2 p = *(const ulonglong2*)(pb + 2 * q);
                bcc0[2 * q]     = ffma2(a.x, wq.x, ffma2(p.x, uq.x, bcc0[2 * q]));
                bcc1[2 * q]     = ffma2(a.x, wq.y, ffma2(p.x, uq.y, bcc1[2 * q]));
                bcc0[2 * q + 1] = ffma2(a.y, wq.x, ffma2(p.y, uq.x, bcc0[2 * q + 1]));
                bcc1[2 * q + 1] = ffma2(a.y, wq.y, ffma2(p.y, uq.y, bcc1[2 * q + 1]));
            }
        }
        #pragma unroll
        for (int j = 0; j < 8; j++) {
            float2 v0 = unpack2(bcc0[j]);
            float2 v1 = unpack2(bcc1[j]);
            *(float2*)(zs + (rh + j) * ZP + 2 * cp)
                = make_float2(b2v.x + v0.x + v0.y, b2v.y + v1.x + v1.y);
        }
        __syncthreads();

        // ---- phase D: layer-2 gates (act = sigmoid) + output store ----
        #pragma unroll
        for (int j = 0; j < 4; j++) {
            int b = eb0 + j;
            const float* zr = zs + b * ZP + eh;
            float ig = sigf(zr[0]);
            float fg = sigf(zr[64]);
            float gg = sigf(zr[128]);
            float og = sigf(zr[192]);
            c2[j] = fmaf(fg, c2[j], ig * gg);
            float hn = og * sigf(c2[j]);
            h2f[ehbase + b * 2] = hn;
            out[(size_t)(b0g + b) * (T_ * H_) + t * H_ + eh] = hn;
        }
        __syncthreads();
    }
}

// ---------------------------------------------------------------------------
extern "C" void kernel_launch(void* const* d_in, const int* in_sizes, int n_in,
                              void* d_out, int out_size)
{
    const float* x  = (const float*)d_in[0];
    const float* W1 = (const float*)d_in[1];
    const float* U1 = (const float*)d_in[2];
    const float* b1 = (const float*)d_in[3];
    const float* W2 = (const float*)d_in[4];
    const float* U2 = (const float*)d_in[5];
    const float* b2 = (const float*)d_in[6];
    float* out = (float*)d_out;

    xz1_gemm_kernel<<<(B_ * T_) / GR, 256>>>(x, W1, b1);

    cudaFuncSetAttribute(lstm_scan_kernel,
                         cudaFuncAttributeMaxDynamicSharedMemorySize, SCAN_SMEM);
    lstm_scan_kernel<<<B_ / BT, 256, SCAN_SMEM>>>(U1, W2, U2, b2, out);
}

// round 11
// speedup vs baseline: 2.4213x; 1.0839x over previous
#include <cuda_runtime.h>

typedef unsigned long long ull;

#define B_ 2048
#define T_ 128
#define D_ 128
#define H_ 64
#define G_ 256   // 4*H

// 128 MB scratch for XZ1, layout [t][b][g]
__device__ float g_xz1[(size_t)T_ * B_ * G_];

// ---------------- f32x2 helpers ----------------
__device__ __forceinline__ ull splat2(float v) {
    ull r; asm("mov.b64 %0,{%1,%1};" : "=l"(r) : "f"(v)); return r;
}
__device__ __forceinline__ ull pack2(float lo, float hi) {
    ull r; asm("mov.b64 %0,{%1,%2};" : "=l"(r) : "f"(lo), "f"(hi)); return r;
}
__device__ __forceinline__ ull ffma2(ull a, ull b, ull c) {
    ull d; asm("fma.rn.f32x2 %0,%1,%2,%3;" : "=l"(d) : "l"(a), "l"(b), "l"(c)); return d;
}
__device__ __forceinline__ float2 unpack2(ull v) {
    float2 f; asm("mov.b64 {%0,%1},%2;" : "=f"(f.x), "=f"(f.y) : "l"(v)); return f;
}
__device__ __forceinline__ float foldz(ull v) {
    float2 f = unpack2(v); return f.x + f.y;
}
__device__ __forceinline__ float sigf(float x) {
    return __fdividef(1.f, 1.f + __expf(-x));
}
__device__ __forceinline__ float tanhf_(float x) {
    return 2.f * __fdividef(1.f, 1.f + __expf(-2.f * x)) - 1.f;
}

// ---------------------------------------------------------------------------
// Kernel 1: XZ1[t][b][g] = sum_d x[m][d] * W1[d][g] + b1[g]  (m = b*T + t)
// (unchanged from round 9 — measured ~384 us)
// ---------------------------------------------------------------------------
#define GR 32
__global__ void __launch_bounds__(256) xz1_gemm_kernel(
    const float* __restrict__ x, const float* __restrict__ W1,
    const float* __restrict__ b1)
{
    __shared__ ull xp[D_ * 16];   // [d][pair], pair p = rows (p, p+16)
    const int tid = threadIdx.x;
    const int m0 = blockIdx.x * GR;

    const float4* xv = (const float4*)x;
    #pragma unroll
    for (int i = 0; i < 2; i++) {
        int u = tid + i * 256;
        int p = u >> 5, c4 = u & 31;
        float4 a = xv[(size_t)(m0 + p) * 32 + c4];
        float4 b = xv[(size_t)(m0 + p + 16) * 32 + c4];
        xp[(4 * c4 + 0) * 16 + p] = pack2(a.x, b.x);
        xp[(4 * c4 + 1) * 16 + p] = pack2(a.y, b.y);
        xp[(4 * c4 + 2) * 16 + p] = pack2(a.z, b.z);
        xp[(4 * c4 + 3) * 16 + p] = pack2(a.w, b.w);
    }
    __syncthreads();

    const int cp = tid & 127;            // cols 2cp, 2cp+1
    const int rh = (tid >> 7) << 3;      // row-pairs rh..rh+7

    const float2 bias = *(const float2*)(b1 + 2 * cp);
    ull acc0[8], acc1[8];
    #pragma unroll
    for (int j = 0; j < 8; j++) { acc0[j] = splat2(bias.x); acc1[j] = splat2(bias.y); }

    const float2* Wp = (const float2*)W1 + cp;     // W1[k][2cp..2cp+1]
    #pragma unroll 4
    for (int k = 0; k < D_; k++) {
        float2 w = Wp[k * 128];
        ull ws0 = splat2(w.x), ws1 = splat2(w.y);
        const ull* xr = xp + k * 16 + rh;
        ulonglong2 q0 = *(const ulonglong2*)(xr);
        ulonglong2 q1 = *(const ulonglong2*)(xr + 2);
        ulonglong2 q2 = *(const ulonglong2*)(xr + 4);
        ulonglong2 q3 = *(const ulonglong2*)(xr + 6);
        acc0[0] = ffma2(q0.x, ws0, acc0[0]); acc1[0] = ffma2(q0.x, ws1, acc1[0]);
        acc0[1] = ffma2(q0.y, ws0, acc0[1]); acc1[1] = ffma2(q0.y, ws1, acc1[1]);
        acc0[2] = ffma2(q1.x, ws0, acc0[2]); acc1[2] = ffma2(q1.x, ws1, acc1[2]);
        acc0[3] = ffma2(q1.y, ws0, acc0[3]); acc1[3] = ffma2(q1.y, ws1, acc1[3]);
        acc0[4] = ffma2(q2.x, ws0, acc0[4]); acc1[4] = ffma2(q2.x, ws1, acc1[4]);
        acc0[5] = ffma2(q2.y, ws0, acc0[5]); acc1[5] = ffma2(q2.y, ws1, acc1[5]);
        acc0[6] = ffma2(q3.x, ws0, acc0[6]); acc1[6] = ffma2(q3.x, ws1, acc1[6]);
        acc0[7] = ffma2(q3.y, ws0, acc0[7]); acc1[7] = ffma2(q3.y, ws1, acc1[7]);
    }

    #pragma unroll
    for (int j = 0; j < 8; j++) {
        float2 va = unpack2(acc0[j]);
        float2 vb = unpack2(acc1[j]);
        int m = m0 + rh + j;
        *(float2*)(g_xz1 + (size_t)(m & 127) * (B_ * G_)
                         + (size_t)(m >> 7) * G_ + 2 * cp) = make_float2(va.x, vb.x);
        m += 16;
        *(float2*)(g_xz1 + (size_t)(m & 127) * (B_ * G_)
                         + (size_t)(m >> 7) * G_ + 2 * cp) = make_float2(va.y, vb.y);
    }
}

// ---------------------------------------------------------------------------
// Kernel 2: fused persistent 2-layer LSTM scan, gate-quad mapping.
// 128 CTAs x 256 threads; CTA owns BT=16 batch rows.
// Thread = hidden unit h (all 4 gates: h, h+64, h+128, h+192) x 4 batch rows.
// GEMM accumulates K-paired f32x2; gates applied in-register (no z smem trip).
// h-state: ping-pong ulonglong2 hh[2][16][32]: .x = h1 K-pair, .y = h2 K-pair.
// 2 barriers per step.
// ---------------------------------------------------------------------------
#define BT 16
// smem: U1kp 64KB | WU2 128KB | hh 2 x 8KB  = 208KB
#define SCAN_SMEM (65536 + 131072 + 2 * 8192)

__global__ void __launch_bounds__(256, 1) lstm_scan_kernel(
    const float* __restrict__ U1g, const float* __restrict__ W2g,
    const float* __restrict__ U2g, const float* __restrict__ b2g,
    float* __restrict__ out)
{
    extern __shared__ char smb[];
    ull* U1kp = (ull*)smb;                                   // [32][256]
    ulonglong2* WU2 = (ulonglong2*)(smb + 65536);            // [32][256] {W2pair, U2pair}
    ulonglong2* hh  = (ulonglong2*)(smb + 65536 + 131072);   // 2 x [16][32]

    const int tid = threadIdx.x;
    const int h  = tid & 63;             // hidden unit
    const int r0 = (tid >> 6) << 2;      // 4 batch rows r0..r0+3
    const int b0g = blockIdx.x * BT;

    for (int i = tid; i < 8192; i += 256) {
        int kk = i >> 8, gg = i & 255;
        U1kp[i] = pack2(U1g[(2 * kk) * G_ + gg], U1g[(2 * kk + 1) * G_ + gg]);
        WU2[i] = make_ulonglong2(
            pack2(W2g[(2 * kk) * G_ + gg], W2g[(2 * kk + 1) * G_ + gg]),
            pack2(U2g[(2 * kk) * G_ + gg], U2g[(2 * kk + 1) * G_ + gg]));
    }
    for (int i = tid; i < 512; i += 256) hh[i] = make_ulonglong2(0ull, 0ull);

    const float bb_i = b2g[h];
    const float bb_f = b2g[64 + h];
    const float bb_g = b2g[128 + h];
    const float bb_o = b2g[192 + h];

    float c1[4] = {0.f, 0.f, 0.f, 0.f};
    float c2[4] = {0.f, 0.f, 0.f, 0.f};
    __syncthreads();

    for (int t = 0; t < T_; t++) {
        ulonglong2* hrd = hh + (t & 1) * 512;         // prev state
        ulonglong2* hwr = hh + ((t & 1) ^ 1) * 512;   // new state
        float* hwrf = (float*)hwr;

        // ---- phase A: z1 = XZ1 + h1_prev @ U1, gates in-register ----
        float xq[4][4];    // [gate][row]
        {
            const float* xp = g_xz1 + ((size_t)t * B_ + b0g + r0) * G_ + h;
            #pragma unroll
            for (int j = 0; j < 4; j++) {
                xq[0][j] = xp[(size_t)j * G_];
                xq[1][j] = xp[(size_t)j * G_ + 64];
                xq[2][j] = xp[(size_t)j * G_ + 128];
                xq[3][j] = xp[(size_t)j * G_ + 192];
            }
        }
        ull ai[4] = {0,0,0,0}, af[4] = {0,0,0,0};
        ull ag[4] = {0,0,0,0}, ao[4] = {0,0,0,0};

        #pragma unroll 4
        for (int kk = 0; kk < 32; kk++) {
            ull ui = U1kp[kk * 256 + h];
            ull uf = U1kp[kk * 256 + 64 + h];
            ull ug = U1kp[kk * 256 + 128 + h];
            ull uo = U1kp[kk * 256 + 192 + h];
            #pragma unroll
            for (int j = 0; j < 4; j++) {
                ull hv = hrd[(r0 + j) * 32 + kk].x;      // bcast LDS.64
                ai[j] = ffma2(hv, ui, ai[j]);
                af[j] = ffma2(hv, uf, af[j]);
                ag[j] = ffma2(hv, ug, ag[j]);
                ao[j] = ffma2(hv, uo, ao[j]);
            }
        }
        #pragma unroll
        for (int j = 0; j < 4; j++) {
            float zi = xq[0][j] + foldz(ai[j]);
            float zf = xq[1][j] + foldz(af[j]);
            float zg = xq[2][j] + foldz(ag[j]);
            float zo = xq[3][j] + foldz(ao[j]);
            float iv = sigf(zi), fv = sigf(zf), gv = tanhf_(zg), ov = sigf(zo);
            c1[j] = fmaf(fv, c1[j], iv * gv);
            hwrf[((r0 + j) * 32 + (h >> 1)) * 4 + (h & 1)] = ov * tanhf_(c1[j]);
        }
        __syncthreads();

        // ---- phase C: z2 = h1_new @ W2 + h2_prev @ U2 + b2, gates in-register ----
        ull bi[4] = {0,0,0,0}, bf[4] = {0,0,0,0};
        ull bg[4] = {0,0,0,0}, bo[4] = {0,0,0,0};

        #pragma unroll 4
        for (int kk = 0; kk < 32; kk++) {
            ulonglong2 qi = WU2[kk * 256 + h];
            ulonglong2 qf = WU2[kk * 256 + 64 + h];
            ulonglong2 qg = WU2[kk * 256 + 128 + h];
            ulonglong2 qo = WU2[kk * 256 + 192 + h];
            #pragma unroll
            for (int j = 0; j < 4; j++) {
                ull h1v = hwr[(r0 + j) * 32 + kk].x;     // h1_new (bcast)
                ull h2v = hrd[(r0 + j) * 32 + kk].y;     // h2_prev (bcast)
                bi[j] = ffma2(h1v, qi.x, ffma2(h2v, qi.y, bi[j]));
                bf[j] = ffma2(h1v, qf.x, ffma2(h2v, qf.y, bf[j]));
                bg[j] = ffma2(h1v, qg.x, ffma2(h2v, qg.y, bg[j]));
                bo[j] = ffma2(h1v, qo.x, ffma2(h2v, qo.y, bo[j]));
            }
        }
        #pragma unroll
        for (int j = 0; j < 4; j++) {
            float zi = bb_i + foldz(bi[j]);
            float zf = bb_f + foldz(bf[j]);
            float zg = bb_g + foldz(bg[j]);
            float zo = bb_o + foldz(bo[j]);
            float iv = sigf(zi), fv = sigf(zf), gv = sigf(zg), ov = sigf(zo);
            c2[j] = fmaf(fv, c2[j], iv * gv);
            float hn = ov * sigf(c2[j]);
            hwrf[((r0 + j) * 32 + (h >> 1)) * 4 + 2 + (h & 1)] = hn;
            out[(size_t)(b0g + r0 + j) * (T_ * H_) + t * H_ + h] = hn;
        }
        __syncthreads();
    }
}

// ---------------------------------------------------------------------------
extern "C" void kernel_launch(void* const* d_in, const int* in_sizes, int n_in,
                              void* d_out, int out_size)
{
    const float* x  = (const float*)d_in[0];
    const float* W1 = (const float*)d_in[1];
    const float* U1 = (const float*)d_in[2];
    const float* b1 = (const float*)d_in[3];
    const float* W2 = (const float*)d_in[4];
    const float* U2 = (const float*)d_in[5];
    const float* b2 = (const float*)d_in[6];
    float* out = (float*)d_out;

    xz1_gemm_kernel<<<(B_ * T_) / GR, 256>>>(x, W1, b1);

    cudaFuncSetAttribute(lstm_scan_kernel,
                         cudaFuncAttributeMaxDynamicSharedMemorySize, SCAN_SMEM);
    lstm_scan_kernel<<<B_ / BT, 256, SCAN_SMEM>>>(U1, W2, U2, b2, out);
}

// round 15
// speedup vs baseline: 2.4283x; 1.0029x over previous
#include <cuda_runtime.h>

typedef unsigned long long ull;

#define B_ 2048
#define T_ 128
#define D_ 128
#define H_ 64
#define G_ 256   // 4*H

// 128 MB scratch for XZ1, layout [t][b][g]
__device__ float g_xz1[(size_t)T_ * B_ * G_];

// ---------------- f32x2 helpers ----------------
__device__ __forceinline__ ull splat2(float v) {
    ull r; asm("mov.b64 %0,{%1,%1};" : "=l"(r) : "f"(v)); return r;
}
__device__ __forceinline__ ull pack2(float lo, float hi) {
    ull r; asm("mov.b64 %0,{%1,%2};" : "=l"(r) : "f"(lo), "f"(hi)); return r;
}
__device__ __forceinline__ ull ffma2(ull a, ull b, ull c) {
    ull d; asm("fma.rn.f32x2 %0,%1,%2,%3;" : "=l"(d) : "l"(a), "l"(b), "l"(c)); return d;
}
__device__ __forceinline__ float2 unpack2(ull v) {
    float2 f; asm("mov.b64 {%0,%1},%2;" : "=f"(f.x), "=f"(f.y) : "l"(v)); return f;
}
__device__ __forceinline__ float foldz(ull v) {
    float2 f = unpack2(v); return f.x + f.y;
}
__device__ __forceinline__ float sigf(float x) {
    return __fdividef(1.f, 1.f + __expf(-x));
}
__device__ __forceinline__ float tanhf_(float x) {
    return 2.f * __fdividef(1.f, 1.f + __expf(-2.f * x)) - 1.f;
}

// ---------------------------------------------------------------------------
// Kernel 1: XZ1[t][b][g] = sum_d x[m][d] * W1[d][g] + b1[g]  (m = b*T + t)
// (unchanged — measured good)
// ---------------------------------------------------------------------------
#define GR 32
__global__ void __launch_bounds__(256) xz1_gemm_kernel(
    const float* __restrict__ x, const float* __restrict__ W1,
    const float* __restrict__ b1)
{
    __shared__ ull xp[D_ * 16];   // [d][pair], pair p = rows (p, p+16)
    const int tid = threadIdx.x;
    const int m0 = blockIdx.x * GR;

    const float4* xv = (const float4*)x;
    #pragma unroll
    for (int i = 0; i < 2; i++) {
        int u = tid + i * 256;
        int p = u >> 5, c4 = u & 31;
        float4 a = xv[(size_t)(m0 + p) * 32 + c4];
        float4 b = xv[(size_t)(m0 + p + 16) * 32 + c4];
        xp[(4 * c4 + 0) * 16 + p] = pack2(a.x, b.x);
        xp[(4 * c4 + 1) * 16 + p] = pack2(a.y, b.y);
        xp[(4 * c4 + 2) * 16 + p] = pack2(a.z, b.z);
        xp[(4 * c4 + 3) * 16 + p] = pack2(a.w, b.w);
    }
    __syncthreads();

    const int cp = tid & 127;
    const int rh = (tid >> 7) << 3;

    const float2 bias = *(const float2*)(b1 + 2 * cp);
    ull acc0[8], acc1[8];
    #pragma unroll
    for (int j = 0; j < 8; j++) { acc0[j] = splat2(bias.x); acc1[j] = splat2(bias.y); }

    const float2* Wp = (const float2*)W1 + cp;
    #pragma unroll 4
    for (int k = 0; k < D_; k++) {
        float2 w = Wp[k * 128];
        ull ws0 = splat2(w.x), ws1 = splat2(w.y);
        const ull* xr = xp + k * 16 + rh;
        ulonglong2 q0 = *(const ulonglong2*)(xr);
        ulonglong2 q1 = *(const ulonglong2*)(xr + 2);
        ulonglong2 q2 = *(const ulonglong2*)(xr + 4);
        ulonglong2 q3 = *(const ulonglong2*)(xr + 6);
        acc0[0] = ffma2(q0.x, ws0, acc0[0]); acc1[0] = ffma2(q0.x, ws1, acc1[0]);
        acc0[1] = ffma2(q0.y, ws0, acc0[1]); acc1[1] = ffma2(q0.y, ws1, acc1[1]);
        acc0[2] = ffma2(q1.x, ws0, acc0[2]); acc1[2] = ffma2(q1.x, ws1, acc1[2]);
        acc0[3] = ffma2(q1.y, ws0, acc0[3]); acc1[3] = ffma2(q1.y, ws1, acc1[3]);
        acc0[4] = ffma2(q2.x, ws0, acc0[4]); acc1[4] = ffma2(q2.x, ws1, acc1[4]);
        acc0[5] = ffma2(q2.y, ws0, acc0[5]); acc1[5] = ffma2(q2.y, ws1, acc1[5]);
        acc0[6] = ffma2(q3.x, ws0, acc0[6]); acc1[6] = ffma2(q3.x, ws1, acc1[6]);
        acc0[7] = ffma2(q3.y, ws0, acc0[7]); acc1[7] = ffma2(q3.y, ws1, acc1[7]);
    }

    #pragma unroll
    for (int j = 0; j < 8; j++) {
        float2 va = unpack2(acc0[j]);
        float2 vb = unpack2(acc1[j]);
        int m = m0 + rh + j;
        *(float2*)(g_xz1 + (size_t)(m & 127) * (B_ * G_)
                         + (size_t)(m >> 7) * G_ + 2 * cp) = make_float2(va.x, vb.x);
        m += 16;
        *(float2*)(g_xz1 + (size_t)(m & 127) * (B_ * G_)
                         + (size_t)(m >> 7) * G_ + 2 * cp) = make_float2(va.y, vb.y);
    }
}

// ---------------------------------------------------------------------------
// Kernel 2: fused persistent 2-layer LSTM scan, gate-quad + narrow-h warps.
// 128 CTAs x 256 threads; CTA owns BT=16 batch rows.
// Warp covers 8 hidden units x 16 rows: lane = h_local*4 + rg;
// thread = hidden unit h (4 gates) x rows {rg, rg+4, rg+8, rg+12}.
// Weight LDS: 8 consecutive addrs x 4-dup = 1 wavefront.
// h-state ping-pong ulonglong2 hh[2][16][HSTR]: .x = h1 K-pair, .y = h2 K-pair,
// HSTR=33 pad so 4 consecutive rows land in distinct banks.
// ---------------------------------------------------------------------------
#define BT 16
#define HSTR 33
// smem: U1kp 64KB | WU2 128KB | hh 2 x 16 x 33 x 16B = 16896B
#define SCAN_SMEM (65536 + 131072 + 2 * 16 * HSTR * 16)

__global__ void __launch_bounds__(256, 1) lstm_scan_kernel(
    const float* __restrict__ U1g, const float* __restrict__ W2g,
    const float* __restrict__ U2g, const float* __restrict__ b2g,
    float* __restrict__ out)
{
    extern __shared__ char smb[];
    ull* U1kp = (ull*)smb;                                   // [32][256]
    ulonglong2* WU2 = (ulonglong2*)(smb + 65536);            // [32][256] {W2pair, U2pair}
    ulonglong2* hh  = (ulonglong2*)(smb + 65536 + 131072);   // 2 x [16][HSTR]

    const int tid = threadIdx.x;
    const int lane = tid & 31;
    const int w = tid >> 5;
    const int h = w * 8 + (lane >> 2);    // 8 h per warp
    const int rg = lane & 3;              // rows rg + 4j, j=0..3
    const int b0g = blockIdx.x * BT;

    for (int i = tid; i < 8192; i += 256) {
        int kk = i >> 8, gg = i & 255;
        U1kp[i] = pack2(U1g[(2 * kk) * G_ + gg], U1g[(2 * kk + 1) * G_ + gg]);
        WU2[i] = make_ulonglong2(
            pack2(W2g[(2 * kk) * G_ + gg], W2g[(2 * kk + 1) * G_ + gg]),
            pack2(U2g[(2 * kk) * G_ + gg], U2g[(2 * kk + 1) * G_ + gg]));
    }
    for (int i = tid; i < 2 * 16 * HSTR; i += 256) hh[i] = make_ulonglong2(0ull, 0ull);

    const float bb_i = b2g[h];
    const float bb_f = b2g[64 + h];
    const float bb_g = b2g[128 + h];
    const float bb_o = b2g[192 + h];

    const int hk = h >> 1;        // state kk slot
    const int hhalf = h & 1;      // float within pair

    float c1[4] = {0.f, 0.f, 0.f, 0.f};
    float c2[4] = {0.f, 0.f, 0.f, 0.f};
    __syncthreads();

    for (int t = 0; t < T_; t++) {
        ulonglong2* hrd = hh + (t & 1) * (16 * HSTR);
        ulonglong2* hwr = hh + ((t & 1) ^ 1) * (16 * HSTR);
        float* hwrf = (float*)hwr;

        // ---- phase A: z1 = XZ1 + h1_prev @ U1, gates in-register ----
        float xq[4][4];    // [gate][j]
        {
            const float* xp = g_xz1 + ((size_t)t * B_ + b0g + rg) * G_ + h;
            #pragma unroll
            for (int j = 0; j < 4; j++) {
                const float* xr = xp + (size_t)(4 * j) * G_;
                xq[0][j] = xr[0];
                xq[1][j] = xr[64];
                xq[2][j] = xr[128];
                xq[3][j] = xr[192];
            }
        }
        ull ai[4] = {0,0,0,0}, af[4] = {0,0,0,0};
        ull ag[4] = {0,0,0,0}, ao[4] = {0,0,0,0};

        #pragma unroll 4
        for (int kk = 0; kk < 32; kk++) {
            ull ui = U1kp[kk * 256 + h];          // 8 distinct -> 1 wf
            ull uf = U1kp[kk * 256 + 64 + h];
            ull ug = U1kp[kk * 256 + 128 + h];
            ull uo = U1kp[kk * 256 + 192 + h];
            #pragma unroll
            for (int j = 0; j < 4; j++) {
                ull hv = hrd[(rg + 4 * j) * HSTR + kk].x;   // 4 consec rows -> 1 wf
                ai[j] = ffma2(hv, ui, ai[j]);
                af[j] = ffma2(hv, uf, af[j]);
                ag[j] = ffma2(hv, ug, ag[j]);
                ao[j] = ffma2(hv, uo, ao[j]);
            }
        }
        #pragma unroll
        for (int j = 0; j < 4; j++) {
            float zi = xq[0][j] + foldz(ai[j]);
            float zf = xq[1][j] + foldz(af[j]);
            float zg = xq[2][j] + foldz(ag[j]);
            float zo = xq[3][j] + foldz(ao[j]);
            float iv = sigf(zi), fv = sigf(zf), gv = tanhf_(zg), ov = sigf(zo);
            c1[j] = fmaf(fv, c1[j], iv * gv);
            hwrf[((rg + 4 * j) * HSTR + hk) * 4 + hhalf] = ov * tanhf_(c1[j]);
        }
        __syncthreads();

        // ---- phase C: z2 = h1_new @ W2 + h2_prev @ U2 + b2 ----
        ull bi[4] = {0,0,0,0}, bf[4] = {0,0,0,0};
        ull bg[4] = {0,0,0,0}, bo[4] = {0,0,0,0};

        #pragma unroll 4
        for (int kk = 0; kk < 32; kk++) {
            ulonglong2 qi = WU2[kk * 256 + h];        // 8 x 16B = 1 wf
            ulonglong2 qf = WU2[kk * 256 + 64 + h];
            ulonglong2 qg = WU2[kk * 256 + 128 + h];
            ulonglong2 qo = WU2[kk * 256 + 192 + h];
            #pragma unroll
            for (int j = 0; j < 4; j++) {
                ull h1v = hwr[(rg + 4 * j) * HSTR + kk].x;   // h1_new
                ull h2v = hrd[(rg + 4 * j) * HSTR + kk].y;   // h2_prev
                bi[j] = ffma2(h1v, qi.x, ffma2(h2v, qi.y, bi[j]));
                bf[j] = ffma2(h1v, qf.x, ffma2(h2v, qf.y, bf[j]));
                bg[j] = ffma2(h1v, qg.x, ffma2(h2v, qg.y, bg[j]));
                bo[j] = ffma2(h1v, qo.x, ffma2(h2v, qo.y, bo[j]));
            }
        }
        #pragma unroll
        for (int j = 0; j < 4; j++) {
            float zi = bb_i + foldz(bi[j]);
            float zf = bb_f + foldz(bf[j]);
            float zg = bb_g + foldz(bg[j]);
            float zo = bb_o + foldz(bo[j]);
            float iv = sigf(zi), fv = sigf(zf), gv = sigf(zg), ov = sigf(zo);
            c2[j] = fmaf(fv, c2[j], iv * gv);
            float hn = ov * sigf(c2[j]);
            hwrf[((rg + 4 * j) * HSTR + hk) * 4 + 2 + hhalf] = hn;
            out[(size_t)(b0g + rg + 4 * j) * (T_ * H_) + t * H_ + h] = hn;
        }
        __syncthreads();
    }
}

// ---------------------------------------------------------------------------
extern "C" void kernel_launch(void* const* d_in, const int* in_sizes, int n_in,
                              void* d_out, int out_size)
{
    const float* x  = (const float*)d_in[0];
    const float* W1 = (const float*)d_in[1];
    const float* U1 = (const float*)d_in[2];
    const float* b1 = (const float*)d_in[3];
    const float* W2 = (const float*)d_in[4];
    const float* U2 = (const float*)d_in[5];
    const float* b2 = (const float*)d_in[6];
    float* out = (float*)d_out;

    xz1_gemm_kernel<<<(B_ * T_) / GR, 256>>>(x, W1, b1);

    cudaFuncSetAttribute(lstm_scan_kernel,
                         cudaFuncAttributeMaxDynamicSharedMemorySize, SCAN_SMEM);
    lstm_scan_kernel<<<B_ / BT, 256, SCAN_SMEM>>>(U1, W2, U2, b2, out);
}